// round 15
// baseline (speedup 1.0000x reference)
#include <cuda_runtime.h>
#include <cuda_fp16.h>
#include <cstdint>

// out[32,11008] = x[32,4096] @ dequant(q[11008,4096]).T
// Single fused kernel: per-block x fp32->fp16 fragment conversion (SMEM),
// mma.sync.m16n8k16 fp16 mainloop (dense q LDG.128 via k-permuted fragments,
// 4-deep prefetch ring), split-K partials + threadfence-counter fused
// reduction (last block per n-tile sums 8 partials, writes out, resets
// counter -> deterministic & graph-replay safe).

#define M_ROWS 32
#define K_DIM  4096
#define N_DIM  11008
#define KSPLIT 8
#define KBLK   (K_DIM / KSPLIT)     // 512 -> 32 k16-steps per block
#define NSTEPS (KBLK / 16)          // 32
#define NWARPS 8
#define NTILE  (NWARPS * 16)        // 128 n per block
#define NNT    (N_DIM / NTILE)      // 86

__device__ float g_part[KSPLIT * (size_t)N_DIM * M_ROWS];   // [ks][n][m]
__device__ int   g_cnt[NNT];                                // zero-init

__device__ __forceinline__ float deq_w(int qi, float s, float z) {
  float qf = __int_as_float(qi | 0x4B000000) - 8388616.0f;  // exact q-8 (Sterbenz)
  return fmaf(qf, s, z);
}
__device__ __forceinline__ uint32_t pack_h2(float lo, float hi) {
  uint32_t r;
  asm("cvt.rn.f16x2.f32 %0, %1, %2;" : "=r"(r) : "f"(hi), "f"(lo));
  return r;
}
__device__ __forceinline__ void mma_f16(float* d, uint32_t a0, uint32_t a1,
                                        uint32_t a2, uint32_t a3,
                                        uint32_t b0, uint32_t b1) {
  asm volatile(
      "mma.sync.aligned.m16n8k16.row.col.f32.f16.f16.f32 "
      "{%0,%1,%2,%3}, {%4,%5,%6,%7}, {%8,%9}, {%0,%1,%2,%3};"
      : "+f"(d[0]), "+f"(d[1]), "+f"(d[2]), "+f"(d[3])
      : "r"(a0), "r"(a1), "r"(a2), "r"(a3), "r"(b0), "r"(b1));
}

__global__ void __launch_bounds__(256, 2)
int4mm_fused_kernel(const int* __restrict__ q, const float* __restrict__ sz,
                    const float* __restrict__ x, float* __restrict__ out) {
  // x fragments for this k-slice: [kb(32)][m(32)][kk(16)] fp16 = 32 KB
  __shared__ __align__(16) unsigned short sx[NSTEPS * M_ROWS * 16];
  __shared__ int s_old;

  const int t    = threadIdx.x;
  const int lane = t & 31;
  const int w    = t >> 5;
  const int gp   = lane >> 2;        // 0..7
  const int c    = lane & 3;         // quad lane -> owns k {4c..4c+3}
  const int ks   = blockIdx.y;
  const int n0   = blockIdx.x * NTILE + w * 16;
  const int kb0  = ks * NSTEPS;      // first k16-step index

  const int rA = n0 + gp;            // A-frag rows (n-dim)
  const int rB = rA + 8;

  const int4*   qA4 = (const int4*)q + (size_t)rA * (K_DIM / 4);
  const int4*   qB4 = (const int4*)q + (size_t)rB * (K_DIM / 4);
  const float2* szp = (const float2*)sz;     // [g][n] {s,z}

  // 4-deep q prefetch ring FIRST (overlaps DRAM latency with x conversion)
  int4 qa_buf[4], qb_buf[4];
#pragma unroll
  for (int i = 0; i < 4; i++) {
    qa_buf[i] = qA4[(kb0 + i) * 4 + c];
    qb_buf[i] = qB4[(kb0 + i) * 4 + c];
  }

  // hoist all 4 groups' scale/zero pairs
  float2 vAg[4], vBg[4];
#pragma unroll
  for (int g = 0; g < 4; g++) {
    const int gg = ks * 4 + g;
    vAg[g] = szp[(size_t)gg * N_DIM + rA];
    vBg[g] = szp[(size_t)gg * N_DIM + rB];
  }

  // ---- convert this block's x slice (fp32 -> fp16 fragment layout in SMEM)
  {
    const int m  = t >> 3;           // 32 m rows, 8 threads each
    const int ko = (t & 7) * 64;     // each thread: 64 contiguous k (128B x2 reads)
    const float2* xp =
        (const float2*)(x + (size_t)m * K_DIM + ks * KBLK + ko);
#pragma unroll
    for (int j = 0; j < 32; j++) {
      float2 v = xp[j];
      int kl = ko + 2 * j;           // local k, even
      uint32_t h2 = pack_h2(v.x, v.y);
      *(uint32_t*)&sx[(kl >> 4) * (M_ROWS * 16) + m * 16 + (kl & 15)] = h2;
    }
  }

  float acc[4][4];
#pragma unroll
  for (int i = 0; i < 4; i++)
#pragma unroll
    for (int j = 0; j < 4; j++) acc[i][j] = 0.0f;

  __syncthreads();                   // sx ready
  const uint2* sx2 = (const uint2*)sx;   // idx = kb*128 + m*4 + c (8B = 4 halves)

  for (int g = 0; g < 4; g++) {
    const float2 vA = vAg[g];
    const float2 vB = vBg[g];
#pragma unroll
    for (int kk = 0; kk < 8; kk++) {
      const int kstep = g * 8 + kk;
      const int4 qa_c = qa_buf[kstep & 3];
      const int4 qb_c = qb_buf[kstep & 3];
      // prefetch step kstep+4 (wrap on tail; harmless valid read)
      const int ksn = (kstep + 4 < NSTEPS) ? (kstep + 4) : 0;
      qa_buf[kstep & 3] = qA4[(kb0 + ksn) * 4 + c];
      qb_buf[kstep & 3] = qB4[(kb0 + ksn) * 4 + c];

      // x fragments from SMEM: xv[mt] = halves x[8mt+gp][4c..4c+3]
      uint2 xv[4];
#pragma unroll
      for (int mt = 0; mt < 4; mt++)
        xv[mt] = sx2[kstep * 128 + (8 * mt + gp) * 4 + c];

      // dequant 8 weights -> 4 packed fp16x2 fragment regs
      float wa0 = deq_w(qa_c.x, vA.x, vA.y), wa1 = deq_w(qa_c.y, vA.x, vA.y);
      float wa2 = deq_w(qa_c.z, vA.x, vA.y), wa3 = deq_w(qa_c.w, vA.x, vA.y);
      float wb0 = deq_w(qb_c.x, vB.x, vB.y), wb1 = deq_w(qb_c.y, vB.x, vB.y);
      float wb2 = deq_w(qb_c.z, vB.x, vB.y), wb3 = deq_w(qb_c.w, vB.x, vB.y);
      uint32_t a0 = pack_h2(wa0, wa1);   // row rA, k {4c, 4c+1}
      uint32_t a1 = pack_h2(wb0, wb1);   // row rB, k {4c, 4c+1}
      uint32_t a2 = pack_h2(wa2, wa3);   // row rA, k {4c+2, 4c+3}
      uint32_t a3 = pack_h2(wb2, wb3);   // row rB, k {4c+2, 4c+3}

#pragma unroll
      for (int mt = 0; mt < 4; mt++)
        mma_f16(acc[mt], a0, a1, a2, a3, xv[mt].x, xv[mt].y);
    }
  }

  // partials: [ks][n][m]; D frag: c0,c1 = (row gp, cols 2c,2c+1), c2,c3 = row gp+8
  float* part = g_part + (size_t)ks * N_DIM * M_ROWS;
#pragma unroll
  for (int mt = 0; mt < 4; mt++) {
    int mcol = 8 * mt + 2 * c;
    *(float2*)&part[(size_t)rA * M_ROWS + mcol] = make_float2(acc[mt][0], acc[mt][1]);
    *(float2*)&part[(size_t)rB * M_ROWS + mcol] = make_float2(acc[mt][2], acc[mt][3]);
  }

  // ---- fused split-K reduction: last block per n-tile sums partials
  __threadfence();                   // make this block's partials visible
  __syncthreads();                   // all threads wrote + fenced
  if (t == 0) s_old = atomicAdd(&g_cnt[blockIdx.x], 1);
  __syncthreads();
  if (s_old == KSPLIT - 1) {         // last arrival: all 8 partial sets visible
    __threadfence();
    const int nbase = blockIdx.x * NTILE;
#pragma unroll
    for (int i = 0; i < (NTILE * M_ROWS) / 256; i++) {
      int idx = t + i * 256;
      int m  = idx >> 7;             // via i: m = (t>>7) + 2i
      int nl = idx & 127;            // = t & 127 (fixed per thread)
      int n  = nbase + nl;
      float s = 0.0f;
#pragma unroll
      for (int k2 = 0; k2 < KSPLIT; k2++)
        s += g_part[(size_t)k2 * N_DIM * M_ROWS + (size_t)n * M_ROWS + m];
      out[(size_t)m * N_DIM + n] = s;   // coalesced in nl
    }
    __syncthreads();
    if (t == 0) g_cnt[blockIdx.x] = 0;  // reset for next graph replay
  }
}

extern "C" void kernel_launch(void* const* d_in, const int* in_sizes, int n_in,
                              void* d_out, int out_size) {
  const float* x  = (const float*)d_in[0];
  const int*   q  = (const int*)d_in[1];
  const float* sz = (const float*)d_in[2];
  float* out = (float*)d_out;

  dim3 grid(NNT, KSPLIT);
  int4mm_fused_kernel<<<grid, 256>>>(q, sz, x, out);
}

// round 16
// speedup vs baseline: 1.1697x; 1.1697x over previous
#include <cuda_runtime.h>
#include <cuda_fp16.h>
#include <cstdint>

// out[32,11008] = x[32,4096] @ dequant(q[11008,4096]).T
// mma.sync.m16n8k16 fp16 (f32 accum), k-permuted fragments (quad c owns
// actual k {4c..4c+3} in both A and B) -> q loads are dense LDG.128,
// x fragment loads are dense LDG.64 from pre-formatted g_xh.
// R16 = R10 body (best, 50.0us) + fused split-K reduction tail (last block
// per n-tile sums 8 partials L2-hot, writes out, resets counter).

#define M_ROWS 32
#define K_DIM  4096
#define N_DIM  11008
#define KSPLIT 8
#define KBLK   (K_DIM / KSPLIT)     // 512 -> 32 k16-steps per block
#define NSTEPS (KBLK / 16)          // 32
#define NWARPS 8
#define NTILE  (NWARPS * 16)        // 128 n per block
#define NNT    (N_DIM / NTILE)      // 86

__device__ float g_part[KSPLIT * (size_t)N_DIM * M_ROWS];   // [ks][n][m]
__device__ unsigned short g_xh[K_DIM * M_ROWS];             // [k16][m(32)][kk(16)] fp16
__device__ int g_cnt[NNT];                                  // zero-init

__device__ __forceinline__ float deq_w(int qi, float s, float z) {
  float qf = __int_as_float(qi | 0x4B000000) - 8388616.0f;  // exact q-8 (Sterbenz)
  return fmaf(qf, s, z);
}
__device__ __forceinline__ uint32_t pack_h2(float lo, float hi) {
  uint32_t r;
  asm("cvt.rn.f16x2.f32 %0, %1, %2;" : "=r"(r) : "f"(hi), "f"(lo));
  return r;
}
__device__ __forceinline__ void mma_f16(float* d, uint32_t a0, uint32_t a1,
                                        uint32_t a2, uint32_t a3,
                                        uint32_t b0, uint32_t b1) {
  asm volatile(
      "mma.sync.aligned.m16n8k16.row.col.f32.f16.f16.f32 "
      "{%0,%1,%2,%3}, {%4,%5,%6,%7}, {%8,%9}, {%0,%1,%2,%3};"
      : "+f"(d[0]), "+f"(d[1]), "+f"(d[2]), "+f"(d[3])
      : "r"(a0), "r"(a1), "r"(a2), "r"(a3), "r"(b0), "r"(b1));
}

// x -> fp16 fragment layout [k/16][m][k%16]
__global__ void xprep_kernel(const float* __restrict__ x) {
  int idx = blockIdx.x * blockDim.x + threadIdx.x;   // one thread per 2 elems
  if (idx >= M_ROWS * K_DIM / 2) return;
  int m  = idx / (K_DIM / 2);
  int k2 = idx % (K_DIM / 2);
  int k  = k2 * 2;
  const float2 v = ((const float2*)x)[idx];
  uint32_t h2 = pack_h2(v.x, v.y);
  *(uint32_t*)&g_xh[(k >> 4) * (M_ROWS * 16) + m * 16 + (k & 15)] = h2;
}

__global__ void __launch_bounds__(256, 2)
int4mm_mma_kernel(const int* __restrict__ q, const float* __restrict__ sz,
                  float* __restrict__ out) {
  __shared__ int s_old;
  const int t    = threadIdx.x;
  const int w    = t >> 5;
  const int lane = t & 31;
  const int gp   = lane >> 2;        // 0..7
  const int c    = lane & 3;         // quad lane -> owns k {4c..4c+3}
  const int ks   = blockIdx.y;
  const int n0   = blockIdx.x * NTILE + w * 16;
  const int kb0  = ks * NSTEPS;      // first k16-step index

  const int rA = n0 + gp;            // A-frag rows (n-dim)
  const int rB = rA + 8;

  float acc[4][4];
#pragma unroll
  for (int i = 0; i < 4; i++)
#pragma unroll
    for (int j = 0; j < 4; j++) acc[i][j] = 0.0f;

  const int4*  qA4 = (const int4*)q + (size_t)rA * (K_DIM / 4);
  const int4*  qB4 = (const int4*)q + (size_t)rB * (K_DIM / 4);
  const uint2* xh2 = (const uint2*)g_xh;     // idx = kb*128 + m*4 + c (8B = 4 halves)
  const float2* szp = (const float2*)sz;     // [g][n] {s,z}

  // hoist all 4 groups' scale/zero pairs
  float2 vAg[4], vBg[4];
#pragma unroll
  for (int g = 0; g < 4; g++) {
    const int gg = ks * 4 + g;
    vAg[g] = szp[(size_t)gg * N_DIM + rA];
    vBg[g] = szp[(size_t)gg * N_DIM + rB];
  }

  // 4-deep q prefetch ring
  int4 qa_buf[4], qb_buf[4];
#pragma unroll
  for (int i = 0; i < 4; i++) {
    qa_buf[i] = qA4[(kb0 + i) * 4 + c];
    qb_buf[i] = qB4[(kb0 + i) * 4 + c];
  }

  for (int g = 0; g < 4; g++) {
    const float2 vA = vAg[g];
    const float2 vB = vBg[g];
#pragma unroll
    for (int kk = 0; kk < 8; kk++) {
      const int kstep = g * 8 + kk;
      const int kb    = kb0 + kstep;
      const int4 qa_c = qa_buf[kstep & 3];
      const int4 qb_c = qb_buf[kstep & 3];
      // prefetch step kstep+4 (wrap on tail; harmless valid read)
      const int ksn = (kstep + 4 < NSTEPS) ? (kstep + 4) : 0;
      qa_buf[kstep & 3] = qA4[(kb0 + ksn) * 4 + c];
      qb_buf[kstep & 3] = qB4[(kb0 + ksn) * 4 + c];

      // x fragments: xv[mt] = halves x[8mt+gp][4c..4c+3] -> b0 = lo, b1 = hi
      uint2 xv[4];
#pragma unroll
      for (int mt = 0; mt < 4; mt++)
        xv[mt] = xh2[(size_t)kb * 128 + (8 * mt + gp) * 4 + c];

      // dequant 8 weights -> 4 packed fp16x2 fragment regs
      float wa0 = deq_w(qa_c.x, vA.x, vA.y), wa1 = deq_w(qa_c.y, vA.x, vA.y);
      float wa2 = deq_w(qa_c.z, vA.x, vA.y), wa3 = deq_w(qa_c.w, vA.x, vA.y);
      float wb0 = deq_w(qb_c.x, vB.x, vB.y), wb1 = deq_w(qb_c.y, vB.x, vB.y);
      float wb2 = deq_w(qb_c.z, vB.x, vB.y), wb3 = deq_w(qb_c.w, vB.x, vB.y);
      uint32_t a0 = pack_h2(wa0, wa1);   // row rA, k {4c, 4c+1}
      uint32_t a1 = pack_h2(wb0, wb1);   // row rB, k {4c, 4c+1}
      uint32_t a2 = pack_h2(wa2, wa3);   // row rA, k {4c+2, 4c+3}
      uint32_t a3 = pack_h2(wb2, wb3);   // row rB, k {4c+2, 4c+3}

#pragma unroll
      for (int mt = 0; mt < 4; mt++)
        mma_f16(acc[mt], a0, a1, a2, a3, xv[mt].x, xv[mt].y);
    }
  }

  // partials: [ks][n][m]; D frag: c0,c1 = (row gp, cols 2c,2c+1), c2,c3 = row gp+8
  float* part = g_part + (size_t)ks * N_DIM * M_ROWS;
#pragma unroll
  for (int mt = 0; mt < 4; mt++) {
    int mcol = 8 * mt + 2 * c;
    *(float2*)&part[(size_t)rA * M_ROWS + mcol] = make_float2(acc[mt][0], acc[mt][1]);
    *(float2*)&part[(size_t)rB * M_ROWS + mcol] = make_float2(acc[mt][2], acc[mt][3]);
  }

  // ---- fused split-K reduction: last block per n-tile sums partials (L2-hot)
  __threadfence();                   // make this block's partials visible
  __syncthreads();                   // all threads wrote + fenced
  if (t == 0) s_old = atomicAdd(&g_cnt[blockIdx.x], 1);
  __syncthreads();
  if (s_old == KSPLIT - 1) {         // last arrival: all 8 partial sets visible
    __threadfence();
    const int nbase = blockIdx.x * NTILE;
#pragma unroll
    for (int i = 0; i < (NTILE * M_ROWS) / 256; i++) {
      int idx = t + i * 256;
      int m  = idx >> 7;
      int nl = idx & 127;
      int n  = nbase + nl;
      float s = 0.0f;
#pragma unroll
      for (int k2 = 0; k2 < KSPLIT; k2++)
        s += g_part[(size_t)k2 * N_DIM * M_ROWS + (size_t)n * M_ROWS + m];
      out[(size_t)m * N_DIM + n] = s;   // coalesced in nl
    }
    __syncthreads();
    if (t == 0) g_cnt[blockIdx.x] = 0;  // reset for next graph replay
  }
}

extern "C" void kernel_launch(void* const* d_in, const int* in_sizes, int n_in,
                              void* d_out, int out_size) {
  const float* x  = (const float*)d_in[0];
  const int*   q  = (const int*)d_in[1];
  const float* sz = (const float*)d_in[2];
  float* out = (float*)d_out;

  xprep_kernel<<<(M_ROWS * K_DIM / 2 + 255) / 256, 256>>>(x);
  dim3 grid(NNT, KSPLIT);
  int4mm_mma_kernel<<<grid, 256>>>(q, sz, out);
}

// round 17
// speedup vs baseline: 2.4087x; 2.0593x over previous
#include <cuda_runtime.h>
#include <cuda_fp16.h>
#include <cstdint>

// out[32,11008] = x[32,4096] @ dequant(q[11008,4096]).T
// mma.sync.m16n8k16 fp16 (f32 accum), k-permuted fragments (quad c owns
// actual k {4c..4c+3} in both A and B) -> q loads are dense LDG.128,
// x fragment loads are dense LDG.64 from pre-formatted g_xh.
// R17 = exact R10 body (best, 50.0us) with:
//   - KSPLIT=16 (wave-quantization: 4.65 waves vs 2.32, tail idle 29%->7%)
//   - __ldcs on q (evict-first L2: protects partials/g_xh residency)
//   - NO fences/atomics in the hot kernel (R15/R16 lesson: threadfence
//     flushes L1D on Blackwell and poisons the q L1 reuse)

#define M_ROWS 32
#define K_DIM  4096
#define N_DIM  11008
#define KSPLIT 16
#define KBLK   (K_DIM / KSPLIT)     // 256 -> 16 k16-steps per block
#define NSTEPS (KBLK / 16)          // 16
#define NWARPS 8
#define NTILE  (NWARPS * 16)        // 128 n per block
#define NNT    (N_DIM / NTILE)      // 86

__device__ float g_part[KSPLIT * (size_t)N_DIM * M_ROWS];   // [ks][n][m] 22.5 MB
__device__ unsigned short g_xh[K_DIM * M_ROWS];             // [k16][m(32)][kk(16)] fp16

__device__ __forceinline__ float deq_w(int qi, float s, float z) {
  float qf = __int_as_float(qi | 0x4B000000) - 8388616.0f;  // exact q-8 (Sterbenz)
  return fmaf(qf, s, z);
}
__device__ __forceinline__ uint32_t pack_h2(float lo, float hi) {
  uint32_t r;
  asm("cvt.rn.f16x2.f32 %0, %1, %2;" : "=r"(r) : "f"(hi), "f"(lo));
  return r;
}
__device__ __forceinline__ void mma_f16(float* d, uint32_t a0, uint32_t a1,
                                        uint32_t a2, uint32_t a3,
                                        uint32_t b0, uint32_t b1) {
  asm volatile(
      "mma.sync.aligned.m16n8k16.row.col.f32.f16.f16.f32 "
      "{%0,%1,%2,%3}, {%4,%5,%6,%7}, {%8,%9}, {%0,%1,%2,%3};"
      : "+f"(d[0]), "+f"(d[1]), "+f"(d[2]), "+f"(d[3])
      : "r"(a0), "r"(a1), "r"(a2), "r"(a3), "r"(b0), "r"(b1));
}

// x -> fp16 fragment layout [k/16][m][k%16]
__global__ void xprep_kernel(const float* __restrict__ x) {
  int idx = blockIdx.x * blockDim.x + threadIdx.x;   // one thread per 2 elems
  if (idx >= M_ROWS * K_DIM / 2) return;
  int m  = idx / (K_DIM / 2);
  int k2 = idx % (K_DIM / 2);
  int k  = k2 * 2;
  const float2 v = ((const float2*)x)[idx];
  uint32_t h2 = pack_h2(v.x, v.y);
  *(uint32_t*)&g_xh[(k >> 4) * (M_ROWS * 16) + m * 16 + (k & 15)] = h2;
}

__global__ void __launch_bounds__(256, 2)
int4mm_mma_kernel(const int* __restrict__ q, const float* __restrict__ sz) {
  const int t    = threadIdx.x;
  const int w    = t >> 5;
  const int lane = t & 31;
  const int gp   = lane >> 2;        // 0..7
  const int c    = lane & 3;         // quad lane -> owns k {4c..4c+3}
  const int ks   = blockIdx.y;
  const int n0   = blockIdx.x * NTILE + w * 16;
  const int kb0  = ks * NSTEPS;      // first k16-step index

  const int rA = n0 + gp;            // A-frag rows (n-dim)
  const int rB = rA + 8;

  float acc[4][4];
#pragma unroll
  for (int i = 0; i < 4; i++)
#pragma unroll
    for (int j = 0; j < 4; j++) acc[i][j] = 0.0f;

  const int4*  qA4 = (const int4*)q + (size_t)rA * (K_DIM / 4);
  const int4*  qB4 = (const int4*)q + (size_t)rB * (K_DIM / 4);
  const uint2* xh2 = (const uint2*)g_xh;     // idx = kb*128 + m*4 + c (8B = 4 halves)
  const float2* szp = (const float2*)sz;     // [g][n] {s,z}

  // hoist both groups' scale/zero pairs (KBLK=256 spans 2 groups of 128)
  float2 vAg[2], vBg[2];
#pragma unroll
  for (int g = 0; g < 2; g++) {
    const int gg = ks * 2 + g;
    vAg[g] = szp[(size_t)gg * N_DIM + rA];
    vBg[g] = szp[(size_t)gg * N_DIM + rB];
  }

  // 4-deep q prefetch ring; __ldcs = streaming (evict-first), q is read-once
  int4 qa_buf[4], qb_buf[4];
#pragma unroll
  for (int i = 0; i < 4; i++) {
    qa_buf[i] = __ldcs(&qA4[(kb0 + i) * 4 + c]);
    qb_buf[i] = __ldcs(&qB4[(kb0 + i) * 4 + c]);
  }

  for (int g = 0; g < 2; g++) {
    const float2 vA = vAg[g];
    const float2 vB = vBg[g];
#pragma unroll
    for (int kk = 0; kk < 8; kk++) {
      const int kstep = g * 8 + kk;
      const int kb    = kb0 + kstep;
      const int4 qa_c = qa_buf[kstep & 3];
      const int4 qb_c = qb_buf[kstep & 3];
      // prefetch step kstep+4 (wrap on tail; harmless valid read)
      const int ksn = (kstep + 4 < NSTEPS) ? (kstep + 4) : 0;
      qa_buf[kstep & 3] = __ldcs(&qA4[(kb0 + ksn) * 4 + c]);
      qb_buf[kstep & 3] = __ldcs(&qB4[(kb0 + ksn) * 4 + c]);

      // x fragments: xv[mt] = halves x[8mt+gp][4c..4c+3] -> b0 = lo, b1 = hi
      uint2 xv[4];
#pragma unroll
      for (int mt = 0; mt < 4; mt++)
        xv[mt] = xh2[(size_t)kb * 128 + (8 * mt + gp) * 4 + c];

      // dequant 8 weights -> 4 packed fp16x2 fragment regs
      float wa0 = deq_w(qa_c.x, vA.x, vA.y), wa1 = deq_w(qa_c.y, vA.x, vA.y);
      float wa2 = deq_w(qa_c.z, vA.x, vA.y), wa3 = deq_w(qa_c.w, vA.x, vA.y);
      float wb0 = deq_w(qb_c.x, vB.x, vB.y), wb1 = deq_w(qb_c.y, vB.x, vB.y);
      float wb2 = deq_w(qb_c.z, vB.x, vB.y), wb3 = deq_w(qb_c.w, vB.x, vB.y);
      uint32_t a0 = pack_h2(wa0, wa1);   // row rA, k {4c, 4c+1}
      uint32_t a1 = pack_h2(wb0, wb1);   // row rB, k {4c, 4c+1}
      uint32_t a2 = pack_h2(wa2, wa3);   // row rA, k {4c+2, 4c+3}
      uint32_t a3 = pack_h2(wb2, wb3);   // row rB, k {4c+2, 4c+3}

#pragma unroll
      for (int mt = 0; mt < 4; mt++)
        mma_f16(acc[mt], a0, a1, a2, a3, xv[mt].x, xv[mt].y);
    }
  }

  // partials: [ks][n][m]; D frag: c0,c1 = (row gp, cols 2c,2c+1), c2,c3 = row gp+8
  float* part = g_part + (size_t)ks * N_DIM * M_ROWS;
#pragma unroll
  for (int mt = 0; mt < 4; mt++) {
    int mcol = 8 * mt + 2 * c;
    *(float2*)&part[(size_t)rA * M_ROWS + mcol] = make_float2(acc[mt][0], acc[mt][1]);
    *(float2*)&part[(size_t)rB * M_ROWS + mcol] = make_float2(acc[mt][2], acc[mt][3]);
  }
}

// sum split-K partials + transpose [n][m] -> out[m][n]  (partials L2-hot via .cs on q)
__global__ void reduce_t_kernel(float* __restrict__ out) {
  __shared__ float sm[32][33];
  const int n0 = blockIdx.x * 32;
  const int xx = threadIdx.x, yy = threadIdx.y;
  float s = 0.0f;
  const size_t off = (size_t)(n0 + yy) * M_ROWS + xx;   // coalesced in xx
#pragma unroll
  for (int ks = 0; ks < KSPLIT; ks++)
    s += g_part[(size_t)ks * N_DIM * M_ROWS + off];
  sm[yy][xx] = s;                     // sm[n_local][m]
  __syncthreads();
  out[(size_t)yy * N_DIM + n0 + xx] = sm[xx][yy];   // coalesced in xx
}

extern "C" void kernel_launch(void* const* d_in, const int* in_sizes, int n_in,
                              void* d_out, int out_size) {
  const float* x  = (const float*)d_in[0];
  const int*   q  = (const int*)d_in[1];
  const float* sz = (const float*)d_in[2];
  float* out = (float*)d_out;

  xprep_kernel<<<(M_ROWS * K_DIM / 2 + 255) / 256, 256>>>(x);
  dim3 grid(NNT, KSPLIT);
  int4mm_mma_kernel<<<grid, 256>>>(q, sz);
  dim3 rblk(32, 32);
  reduce_t_kernel<<<N_DIM / 32, rblk>>>(out);
}